// round 13
// baseline (speedup 1.0000x reference)
#include <cuda_runtime.h>
#include <cuda_bf16.h>
#include <cstdint>

#define C 80
#define SLAB 8                  // items per warp-slab
#define PITCH 88                // halves per item row (80+8 pad)
#define PITCHB (PITCH * 2)      // 176 bytes
#define NTHREADS 128            // 4 independent warps
#define GRID 444                // 3 CTAs/SM x 148
#define NSTREAMS (GRID * 4)     // fully independent warp streams

__device__ float g_cooc[C * C];
__device__ unsigned int g_count;

__device__ const int g_pbi[15] = {0,0,0,0,0,1,1,1,1,2,2,2,3,3,4};
__device__ const int g_pbj[15] = {0,1,2,3,4,1,2,3,4,2,3,4,3,4,4};

#define MMA8(acc, A0, A1, B0) \
    asm volatile("mma.sync.aligned.m16n8k8.row.col.f32.bf16.bf16.f32 " \
                 "{%0,%1,%2,%3}, {%4,%5}, {%6}, {%0,%1,%2,%3};" \
                 : "+f"((acc)[0]), "+f"((acc)[1]), "+f"((acc)[2]), "+f"((acc)[3]) \
                 : "r"(A0), "r"(A1), "r"(B0))

static __device__ __forceinline__ uint32_t pack_bf16x2(float x, float y) {
    uint32_t r;
    asm("prmt.b32 %0, %1, %2, 0x7632;" : "=r"(r)
        : "r"(__float_as_uint(x)), "r"(__float_as_uint(y)));
    return r;
}

__global__ __launch_bounds__(NTHREADS, 3)
void fused_kernel(const float* __restrict__ label,
                  const float* __restrict__ pre_adj,
                  float* __restrict__ out, int batch) {
    __shared__ __align__(16) __nv_bfloat16 slab[4 * SLAB * PITCH];   // 4 private strips
    __shared__ float sRed[15 * 256];
    __shared__ float red[4];
    __shared__ int s_last;

    const int tid  = threadIdx.x;
    const int warp = tid >> 5;
    const int lane = tid & 31;
    const int g    = lane >> 2;
    const int t    = lane & 3;
    const int li   = lane & 7;
    const int lq   = lane >> 3;

    for (int i = tid; i < 15 * 256; i += NTHREADS) sRed[i] = 0.0f;
    __syncthreads();

    const uint32_t sb =
        (uint32_t)__cvta_generic_to_shared(slab) + (uint32_t)(warp * SLAB * PITCHB);

    // ldmatrix.trans lane addresses: tile q = classes 8q..8q+7, rows = items
    const uint32_t lm0 = sb + (uint32_t)(li * PITCHB + lq * 16);            // tiles 0-3
    const uint32_t lm1 = lm0 + 64u;                                         // tiles 4-7
    const uint32_t lm2 = sb + (uint32_t)(li * PITCHB + (8 + (lq & 1)) * 16);// tiles 8-9

    float d[30][4];
    #pragma unroll
    for (int p = 0; p < 30; p++)
        #pragma unroll
        for (int q = 0; q < 4; q++) d[p][q] = 0.0f;

    const int numSlabs = batch / SLAB;
    int s = blockIdx.x * 4 + warp;

    float4 st[5];
    if (s < numSlabs) {
        const float* pb = label + (long long)s * SLAB * C;
        #pragma unroll
        for (int p = 0; p < 5; p++) {
            int chunk = lane + p * 32;
            st[p] = *(const float4*)(pb + (chunk / 20) * C + (chunk % 20) * 4);
        }
    }

    while (s < numSlabs) {
        // ---- pack + store own slab (warp-private strip) ----
        #pragma unroll
        for (int p = 0; p < 5; p++) {
            int chunk = lane + p * 32;
            uint32_t sa = sb + (uint32_t)((chunk / 20) * PITCHB + (chunk % 20) * 8);
            uint32_t lo = pack_bf16x2(st[p].x, st[p].y);
            uint32_t hi = pack_bf16x2(st[p].z, st[p].w);
            asm volatile("st.shared.v2.b32 [%0], {%1,%2};"
                         :: "r"(sa), "r"(lo), "r"(hi) : "memory");
        }

        // ---- prefetch next slab for this stream (full iteration of slack) ----
        const int nxt = s + NSTREAMS;
        if (nxt < numSlabs) {
            const float* pb = label + (long long)nxt * SLAB * C;
            #pragma unroll
            for (int p = 0; p < 5; p++) {
                int chunk = lane + p * 32;
                st[p] = *(const float4*)(pb + (chunk / 20) * C + (chunk % 20) * 4);
            }
        }

        __syncwarp();   // own stores visible to own collective ldmatrix

        // ---- load all ten 8x8 class tiles (3 LDSM ops, 10 regs) ----
        uint32_t tl[10];
        asm volatile("ldmatrix.sync.aligned.m8n8.x4.trans.shared.b16 {%0,%1,%2,%3}, [%4];"
                     : "=r"(tl[0]), "=r"(tl[1]), "=r"(tl[2]), "=r"(tl[3]) : "r"(lm0));
        asm volatile("ldmatrix.sync.aligned.m8n8.x4.trans.shared.b16 {%0,%1,%2,%3}, [%4];"
                     : "=r"(tl[4]), "=r"(tl[5]), "=r"(tl[6]), "=r"(tl[7]) : "r"(lm1));
        asm volatile("ldmatrix.sync.aligned.m8n8.x2.trans.shared.b16 {%0,%1}, [%2];"
                     : "=r"(tl[8]), "=r"(tl[9]) : "r"(lm2));

        // ---- 30 symmetric (m16, n8) blocks, K=8, zero sync ----
        {
            int idx = 0;
            #pragma unroll
            for (int m = 0; m < 5; m++) {
                #pragma unroll
                for (int j = 2 * m; j < 10; j++) {
                    MMA8(d[idx], tl[2 * m], tl[2 * m + 1], tl[j]);
                    idx++;
                }
            }
        }

        s = nxt;
    }

    // ---- flush accumulators into per-CTA smem blocks (exact ints) ----
    {
        int idx = 0;
        #pragma unroll
        for (int m = 0; m < 5; m++) {
            #pragma unroll
            for (int j = 2 * m; j < 10; j++) {
                const int slot = (m * 5 + (j >> 1) - (m * (m + 1)) / 2) * 256;
                const int cb   = (j & 1) * 8 + 2 * t;
                atomicAdd(&sRed[slot + (g)     * 16 + cb],     d[idx][0]);
                atomicAdd(&sRed[slot + (g)     * 16 + cb + 1], d[idx][1]);
                atomicAdd(&sRed[slot + (g + 8) * 16 + cb],     d[idx][2]);
                atomicAdd(&sRed[slot + (g + 8) * 16 + cb + 1], d[idx][3]);
                idx++;
            }
        }
    }
    __syncthreads();

    // ---- one global flush per CTA ----
    for (int idx = tid; idx < 15 * 256; idx += NTHREADS) {
        const int slot = idx >> 8, e = idx & 255;
        const int i = g_pbi[slot] * 16 + (e >> 4);
        const int j = g_pbj[slot] * 16 + (e & 15);
        atomicAdd(&g_cooc[i * C + j], sRed[idx]);
    }

    // ---- last-CTA finalize ----
    __threadfence();
    __syncthreads();
    if (tid == 0)
        s_last = (atomicAdd(&g_count, 1u) == (unsigned)gridDim.x - 1u) ? 1 : 0;
    __syncthreads();
    if (!s_last) return;

    float sum = 0.0f;
    for (int idx = tid; idx < C * C; idx += NTHREADS) {
        int i = idx / C, j = idx - i * C;
        int bi = i >> 4, bj = j >> 4;
        float cooc = (bi <= bj) ? g_cooc[i * C + j] : g_cooc[j * C + i];  // upper blocks stored
        float cnt  = g_cooc[i * C + i];
        float adj  = (i == j) ? 1.0f : __fdividef(cooc, cnt + 1e-7f);
        float r = fabsf(pre_adj[idx] - adj);
        sum += (r < 1.0f) ? (r * r) : (r - 0.5f);
    }
    #pragma unroll
    for (int o = 16; o > 0; o >>= 1) sum += __shfl_down_sync(0xffffffffu, sum, o);
    if (lane == 0) red[warp] = sum;
    __syncthreads();
    if (warp == 0) {
        float v = (lane < 4) ? red[lane] : 0.0f;
        #pragma unroll
        for (int o = 16; o > 0; o >>= 1) v += __shfl_down_sync(0xffffffffu, v, o);
        if (lane == 0) out[0] = v / (float)(C * C);
    }
    __syncthreads();   // all g_cooc reads complete before re-zero
    for (int idx = tid; idx < C * C; idx += NTHREADS) g_cooc[idx] = 0.0f;
    if (tid == 0) g_count = 0u;
}

extern "C" void kernel_launch(void* const* d_in, const int* in_sizes, int n_in,
                              void* d_out, int out_size) {
    const float* pre_adj = (const float*)d_in[0];
    const float* label   = (const float*)d_in[1];
    const int batch = in_sizes[1] / C;

    fused_kernel<<<GRID, NTHREADS>>>(label, pre_adj, (float*)d_out, batch);
}